// round 13
// baseline (speedup 1.0000x reference)
#include <cuda_runtime.h>
#include <cuda_fp16.h>
#include <cstdint>
#include <cstddef>

// Problem sizes
#define HH     256
#define BB     256
#define TT     512
#define DD     64
#define NCLASS 10

// Topology: 16 clusters x 8 CTAs; cluster owns 16 batch rows; CTA owns 32 j.
#define CS   8
#define NC   16
#define BC   16
#define RTH  512   // 16 warps: warp = (mt = w&7, nt = w>>3)

// ---- SMEM layout (bytes) ----
// A-lo (h-part):  [8 mt][16 kt][128 u32] = 65536
// A-x hi/lo:      [8 mt][4 kt][128 u32]  = 16384 each
// x frags:        [2 bufs][512 u32] hi + lo = 4096 each
#define SM_AL  0
#define SM_AXH (SM_AL + 8 * 16 * 512)
#define SM_AXL (SM_AXH + 8 * 4 * 512)
#define SM_XHI (SM_AXL + 8 * 4 * 512)
#define SM_XLO (SM_XHI + 2 * 512 * 4)
#define SM_TOTAL (SM_XLO + 2 * 512 * 4)   // 106496

// h exchange: B-fragment-layout image, per parity (VERIFIED layout from R9-R12):
// word (kt*2+nt)*64 + l*2 + jreg : k = 16*kt + 2*(l&3) + 8*jreg (k,k+1 packed
// in the two u16 halves), n = nt*8 + (l>>2)
__device__ uint32_t g_hfrag[2][NC][2][2048];   // [parity][cluster][hi/lo][word]
__device__ float g_hT[BB * HH];

// ---------------------------------------------------------------------------
__device__ __forceinline__ float sigm(float x) { return 1.0f / (1.0f + __expf(-x)); }
__device__ __forceinline__ float tanh_fast(float x) {
    return 1.0f - 2.0f / (__expf(2.0f * x) + 1.0f);
}
__device__ __forceinline__ uint32_t split_pack(float a, float b, uint32_t& lo) {
    __half ah = __float2half_rn(a), bh = __float2half_rn(b);
    __half al = __float2half_rn(a - __half2float(ah));
    __half bl = __float2half_rn(b - __half2float(bh));
    __half2 h2 = __halves2half2(ah, bh), l2 = __halves2half2(al, bl);
    lo = *reinterpret_cast<uint32_t*>(&l2);
    return *reinterpret_cast<uint32_t*>(&h2);
}
__device__ __forceinline__ void mma16816(float* d, const uint32_t* a, const uint32_t* b) {
    asm volatile(
        "mma.sync.aligned.m16n8k16.row.col.f32.f16.f16.f32 "
        "{%0,%1,%2,%3}, {%4,%5,%6,%7}, {%8,%9}, {%0,%1,%2,%3};"
        : "+f"(d[0]), "+f"(d[1]), "+f"(d[2]), "+f"(d[3])
        : "r"(a[0]), "r"(a[1]), "r"(a[2]), "r"(a[3]), "r"(b[0]), "r"(b[1]));
}
// Karatsuba k-tile: hi*hi + hi*lo + lo*hi into one accumulator.
__device__ __forceinline__ void mma3(float* acc, const uint32_t* ahi,
                                     const uint32_t* alo, uint2 vh, uint2 vl) {
    uint32_t ph[2] = {vh.x, vh.y};
    uint32_t pl[2] = {vl.x, vl.y};
    mma16816(acc, ahi, ph);
    mma16816(acc, ahi, pl);
    mma16816(acc, alo, ph);
}
__device__ __forceinline__ void stg_u16(void* p, unsigned short v) {
    asm volatile("st.global.cg.u16 [%0], %1;" :: "l"(p), "h"(v) : "memory");
}
#define CLU_ARRIVE() asm volatile("barrier.cluster.arrive.aligned;" ::: "memory")
#define CLU_WAIT()   asm volatile("barrier.cluster.wait.aligned;"   ::: "memory")

// ---------------------------------------------------------------------------
// A-row remap (gate-interleaved so pointwise is in-register):
//   m = mt*16 + (g&1)*8 + (g>>1)*4 + (jl&3),  jl = 4*mt + (m&3)
// D frag of warp (mt,nt), lane l (rr=l>>2, cc=l&3):
//   acc d0=(rr,c0) d1=(rr,c0+1) d2=(rr+8,c0) d3=(rr+8,c0+1), c0=2*cc
//   rows rr,rr+8 = gates {2*(rr>>2), 2*(rr>>2)+1} of jl=4mt+(rr&3)
//   lane l^16 holds the other gate pair -> one shfl_xor(16) completes the cell.
// ---------------------------------------------------------------------------
__global__ __launch_bounds__(RTH, 1) __cluster_dims__(CS, 1, 1)
void lstm_kernel(const float* __restrict__ x,
                 const float* __restrict__ Wih,
                 const float* __restrict__ Whh,
                 const float* __restrict__ bih,
                 const float* __restrict__ bhh,
                 const float* __restrict__ Wout,
                 const float* __restrict__ bout,
                 float* __restrict__ out) {
    extern __shared__ __align__(16) char smc[];
    const int tid = threadIdx.x;
    const int wid = tid >> 5, lan = tid & 31;
    const int mt = wid & 7, nt = wid >> 3;
    const int cta = blockIdx.x, q = cta / CS, r = cta % CS;

    uint32_t* Al  = reinterpret_cast<uint32_t*>(smc + SM_AL);
    uint32_t* Axh = reinterpret_cast<uint32_t*>(smc + SM_AXH);
    uint32_t* Axl = reinterpret_cast<uint32_t*>(smc + SM_AXL);
    uint32_t* Xhi = reinterpret_cast<uint32_t*>(smc + SM_XHI);
    uint32_t* Xlo = reinterpret_cast<uint32_t*>(smc + SM_XLO);

    // ---- zero parity-0 h image (h0 = 0) ----
    if (tid < 128)
        reinterpret_cast<uint4*>(&g_hfrag[0][q][0][0])[r * 128 + tid] =
            make_uint4(0u, 0u, 0u, 0u);

    // ---- build A fragments with gate-remapped rows ----
    uint32_t Ah[16][4];
#pragma unroll
    for (int kt = 0; kt < 16; kt++) {
#pragma unroll
        for (int reg = 0; reg < 4; reg++) {
            int i  = (lan >> 2) + 8 * (reg & 1);           // row within tile
            int g  = ((i >> 2) & 1) * 2 + ((i >> 3) & 1);
            int jl = 4 * mt + (i & 3);
            int row = g * HH + r * 32 + jl;
            int kk = 16 * kt + 2 * (lan & 3) + 8 * (reg >> 1);
            float2 v = *reinterpret_cast<const float2*>(&Whh[(size_t)row * HH + kk]);
            uint32_t lo, hi = split_pack(v.x, v.y, lo);
            Ah[kt][reg] = hi;
            if (nt == 0) Al[(mt * 16 + kt) * 128 + lan * 4 + reg] = lo;
        }
    }
    if (nt == 0) {
#pragma unroll
        for (int kt = 0; kt < 4; kt++) {
#pragma unroll
            for (int reg = 0; reg < 4; reg++) {
                int i  = (lan >> 2) + 8 * (reg & 1);
                int g  = ((i >> 2) & 1) * 2 + ((i >> 3) & 1);
                int jl = 4 * mt + (i & 3);
                int row = g * HH + r * 32 + jl;
                int kk = 16 * kt + 2 * (lan & 3) + 8 * (reg >> 1);   // 0..63
                float2 v = *reinterpret_cast<const float2*>(&Wih[(size_t)row * DD + kk]);
                uint32_t lo, hi = split_pack(v.x, v.y, lo);
                Axh[(mt * 4 + kt) * 128 + lan * 4 + reg] = hi;
                Axl[(mt * 4 + kt) * 128 + lan * 4 + reg] = lo;
            }
        }
    }

    // ---- pointwise cell ownership: (jl_own, b_own) per thread ----
    const int rr = lan >> 2;
    const int sel = (lan >> 4) & 1;                 // = rr>>2
    const int jl_own = 4 * mt + (rr & 3);
    const int b_own  = nt * 8 + 2 * (lan & 3) + sel;
    const int jg = r * 32 + jl_own;
    float bz[4];
#pragma unroll
    for (int g = 0; g < 4; g++)
        bz[g] = bih[g * HH + jg] + bhh[g * HH + jg];

    // h-writer byte offset into the fragment image (u16 granularity)
    size_t hbyte;
    {
        int ktw = jg >> 4, rem = jg & 15;
        int jreg = (rem >> 3) & 1, lpart = (rem & 7) >> 1, half = rem & 1;
        int lanew = (b_own & 7) * 4 + lpart;
        int word = ((ktw * 2) + (b_own >> 3)) * 64 + lanew * 2 + jreg;
        hbyte = (size_t)word * 4 + half * 2;
    }

    // ---- x-frag ownership (threads 0..255): words {2*tp, 2*tp+1} of 512 ----
    const int tp = tid & 255;
    const int xktn = tp >> 5;
    const int xln  = tp & 31;
    const int xn   = (xktn & 1) * 8 + (xln >> 2);
    const int xd0  = (xktn >> 1) * 16 + 2 * (xln & 3);
    const float* xrow = x + ((size_t)(q * BC + xn) * TT) * DD;
    float2 pva = make_float2(0.f, 0.f), pvb = make_float2(0.f, 0.f);
    if (tid < 256) {
        float2 va = *reinterpret_cast<const float2*>(xrow + xd0);
        float2 vb = *reinterpret_cast<const float2*>(xrow + xd0 + 8);
        uint32_t lo0, hi0 = split_pack(va.x, va.y, lo0);
        uint32_t lo1, hi1 = split_pack(vb.x, vb.y, lo1);
        *reinterpret_cast<uint2*>(Xhi + 2 * tp) = make_uint2(hi0, hi1);
        *reinterpret_cast<uint2*>(Xlo + 2 * tp) = make_uint2(lo0, lo1);
        pva = *reinterpret_cast<const float2*>(xrow + DD + xd0);
        pvb = *reinterpret_cast<const float2*>(xrow + DD + xd0 + 8);
    }

    float cst = 0.0f;
    __syncthreads();
    CLU_ARRIVE();   // publish zeroed h image

    for (int t = 0; t < TT; t++) {
        float a0[4] = {0.f, 0.f, 0.f, 0.f};
        float a1[4] = {0.f, 0.f, 0.f, 0.f};
        float a2[4] = {0.f, 0.f, 0.f, 0.f};
        float a3[4] = {0.f, 0.f, 0.f, 0.f};

        // ---- x-part MMAs from local smem (hides cluster barrier skew) ----
        {
            const uint32_t* xh = Xhi + (t & 1) * 512;
            const uint32_t* xl = Xlo + (t & 1) * 512;
#pragma unroll
            for (int k4 = 0; k4 < 4; k4++) {
                int tb = (k4 * 2 + nt) * 64 + lan * 2;
                uint2 bh = *reinterpret_cast<const uint2*>(xh + tb);
                uint2 bl = *reinterpret_cast<const uint2*>(xl + tb);
                uint4 axh = *reinterpret_cast<const uint4*>(Axh + (mt * 4 + k4) * 128 + lan * 4);
                uint4 axl = *reinterpret_cast<const uint4*>(Axl + (mt * 4 + k4) * 128 + lan * 4);
                uint32_t ahx[4] = {axh.x, axh.y, axh.z, axh.w};
                uint32_t alx[4] = {axl.x, axl.y, axl.z, axl.w};
                float* acc = (k4 == 0) ? a0 : (k4 == 1) ? a1 : (k4 == 2) ? a2 : a3;
                mma3(acc, ahx, alx, bh, bl);
            }
        }

        CLU_WAIT();   // peers' h(t-1) frags visible

        // ---- h-part MMAs: B frags straight from L2, 4 rotating acc chains ----
        {
            const uint32_t* ghi = &g_hfrag[t & 1][q][0][0];
            const uint32_t* glo = &g_hfrag[t & 1][q][1][0];
#pragma unroll
            for (int kt = 0; kt < 16; kt++) {
                int tb = (kt * 2 + nt) * 64 + lan * 2;
                uint2 bh = __ldcg(reinterpret_cast<const uint2*>(ghi + tb));
                uint2 bl = __ldcg(reinterpret_cast<const uint2*>(glo + tb));
                uint4 al4 = *reinterpret_cast<const uint4*>(Al + (mt * 16 + kt) * 128 + lan * 4);
                uint32_t alr[4] = {al4.x, al4.y, al4.z, al4.w};
                float* acc = ((kt & 3) == 0) ? a0 : ((kt & 3) == 1) ? a1
                           : ((kt & 3) == 2) ? a2 : a3;
                mma3(acc, Ah[kt], alr, bh, bl);
            }
        }

        // ---- combine chains, exchange gate pairs, pointwise in-register ----
        float d0 = a0[0] + a1[0] + a2[0] + a3[0];
        float d1 = a0[1] + a1[1] + a2[1] + a3[1];
        float d2 = a0[2] + a1[2] + a2[2] + a3[2];
        float d3 = a0[3] + a1[3] + a2[3] + a3[3];

        float sA = sel ? d0 : d1;
        float sB = sel ? d2 : d3;
        float rA = __shfl_xor_sync(0xffffffffu, sA, 16);
        float rB = __shfl_xor_sync(0xffffffffu, sB, 16);

        float zi, zf, zg, zo;
        if (!sel) { zi = d0; zf = d2; zg = rA; zo = rB; }
        else      { zi = rA; zf = rB; zg = d1; zo = d3; }
        zi += bz[0]; zf += bz[1]; zg += bz[2]; zo += bz[3];

        float cv = sigm(zf) * cst + sigm(zi) * tanh_fast(zg);
        cst = cv;
        float h = sigm(zo) * tanh_fast(cv);

        // ---- write h (2 x u16) into next-parity fragment image ----
        {
            __half hh = __float2half_rn(h);
            __half hl = __float2half_rn(h - __half2float(hh));
            char* bhi = reinterpret_cast<char*>(&g_hfrag[(t + 1) & 1][q][0][0]);
            char* blo = reinterpret_cast<char*>(&g_hfrag[(t + 1) & 1][q][1][0]);
            stg_u16(bhi + hbyte, __half_as_ushort(hh));
            stg_u16(blo + hbyte, __half_as_ushort(hl));
            if (t == TT - 1)
                __stcg(&g_hT[(q * BC + b_own) * HH + jg], h);
        }

        // ---- publish x(t+1), prefetch x(t+2) ----
        if (tid < 256 && t + 1 < TT) {
            uint32_t lo0, hi0 = split_pack(pva.x, pva.y, lo0);
            uint32_t lo1, hi1 = split_pack(pvb.x, pvb.y, lo1);
            uint32_t* xh = Xhi + ((t + 1) & 1) * 512;
            uint32_t* xl = Xlo + ((t + 1) & 1) * 512;
            *reinterpret_cast<uint2*>(xh + 2 * tp) = make_uint2(hi0, hi1);
            *reinterpret_cast<uint2*>(xl + 2 * tp) = make_uint2(lo0, lo1);
            if (t + 2 < TT) {
                pva = *reinterpret_cast<const float2*>(xrow + (size_t)(t + 2) * DD + xd0);
                pvb = *reinterpret_cast<const float2*>(xrow + (size_t)(t + 2) * DD + xd0 + 8);
            }
        }
        __syncthreads();   // x(t+1) frags ready for next iteration
        CLU_ARRIVE();      // release h(t)
    }
    CLU_WAIT();

    // ---- output head: CTA handles batches {2r, 2r+1}; 20 tasks / 16 warps ----
    for (int task = wid; task < 2 * NCLASS; task += 16) {
        int row = task / NCLASS, cls = task % NCLASS;
        int b = q * BC + 2 * r + row;
        float s = 0.0f;
#pragma unroll
        for (int k = lan; k < HH; k += 32)
            s += __ldcg(&g_hT[b * HH + k]) * Wout[cls * HH + k];
#pragma unroll
        for (int o = 16; o; o >>= 1) s += __shfl_xor_sync(0xffffffffu, s, o);
        if (lan == 0) out[b * NCLASS + cls] = sigm(s + bout[cls]);
    }
}

extern "C" void kernel_launch(void* const* d_in, const int* in_sizes, int n_in,
                              void* d_out, int out_size) {
    const float* x    = (const float*)d_in[0];
    const float* Wih  = (const float*)d_in[1];
    const float* Whh  = (const float*)d_in[2];
    const float* bih  = (const float*)d_in[3];
    const float* bhh  = (const float*)d_in[4];
    const float* Wout = (const float*)d_in[5];
    const float* bout = (const float*)d_in[6];
    float* out = (float*)d_out;

    cudaFuncSetAttribute(lstm_kernel,
                         cudaFuncAttributeMaxDynamicSharedMemorySize, SM_TOTAL);

    lstm_kernel<<<NC * CS, RTH, SM_TOTAL>>>(x, Wih, Whh, bih, bhh,
                                            Wout, bout, out);
}